// round 13
// baseline (speedup 1.0000x reference)
#include <cuda_runtime.h>
#include <cuda_bf16.h>
#include <math.h>
#include <stdint.h>

#define B_  2
#define T_  1024
#define D_  1024
#define H_  16
#define HD_ 64
#define FF_ 4096
#define L_  4
#define MREL 128
#define BT_ (B_*T_)   // 2048

// ---------------- scratch (no allocs allowed) ----------------
__device__ float g_h[BT_*D_];          // 8 MB
__device__ float g_tmp[BT_*D_];        // 8 MB
__device__ float g_qkv[BT_*3*D_];      // 24 MB
__device__ float g_ff1[BT_*2*FF_];     // 64 MB

// bf16x2-packed activations (hi/lo), max M*K = 2048*4096
__device__ uint32_t g_ah[(size_t)BT_*FF_/2];
__device__ uint32_t g_al[(size_t)BT_*FF_/2];

// attention operands, bf16x2 words
__device__ uint32_t g_qh[(size_t)B_*H_*T_*32];  // [bh][t][d2]
__device__ uint32_t g_ql[(size_t)B_*H_*T_*32];
__device__ uint32_t g_kh[(size_t)B_*H_*32*T_];  // [bh][d2][t]
__device__ uint32_t g_kl[(size_t)B_*H_*32*T_];
__device__ uint32_t g_vh[(size_t)B_*H_*512*64]; // [bh][t2][d]
__device__ uint32_t g_vl[(size_t)B_*H_*512*64];

// bf16x2-packed weights (hi/lo), word layout [K/2][N]
#define WOFF_IN   ((size_t)0)
#define WSZ_IN    ((size_t)D_*D_/2)
#define WOFF_QKV  (WOFF_IN + WSZ_IN)
#define WSZ_QKV   ((size_t)D_*3*D_/2)
#define WOFF_PROJ (WOFF_QKV + L_*WSZ_QKV)
#define WSZ_PROJ  ((size_t)D_*D_/2)
#define WOFF_FC1  (WOFF_PROJ + L_*WSZ_PROJ)
#define WSZ_FC1   ((size_t)D_*2*FF_/2)
#define WOFF_FC2  (WOFF_FC1 + L_*WSZ_FC1)
#define WSZ_FC2   ((size_t)FF_*D_/2)
#define WOFF_OUT  (WOFF_FC2 + L_*WSZ_FC2)
#define WTOT      (WOFF_OUT + (size_t)D_*D_/2)
__device__ uint32_t g_wh[WTOT];
__device__ uint32_t g_wl[WTOT];

// ---------------- helpers ----------------
__device__ __forceinline__ uint32_t smem_u32(const void* p) {
    uint32_t a;
    asm("{ .reg .u64 t; cvta.to.shared.u64 t, %1; cvt.u32.u64 %0, t; }" : "=r"(a) : "l"(p));
    return a;
}
__device__ __forceinline__ uint32_t pack_hi(float a, float b, float& ra, float& rb) {
    __nv_bfloat16 ba = __float2bfloat16_rn(a), bb = __float2bfloat16_rn(b);
    ra = a - __bfloat162float(ba);
    rb = b - __bfloat162float(bb);
    uint16_t ua = *(uint16_t*)&ba, ub = *(uint16_t*)&bb;
    return (uint32_t)ua | ((uint32_t)ub << 16);
}
__device__ __forceinline__ uint32_t pack_lo(float ra, float rb) {
    __nv_bfloat16 ba = __float2bfloat16_rn(ra), bb = __float2bfloat16_rn(rb);
    uint16_t ua = *(uint16_t*)&ba, ub = *(uint16_t*)&bb;
    return (uint32_t)ua | ((uint32_t)ub << 16);
}
__device__ __forceinline__ void cp16(uint32_t dst, const void* src) {
    asm volatile("cp.async.cg.shared.global [%0], [%1], 16;" :: "r"(dst), "l"(src));
}
#define CP_COMMIT() asm volatile("cp.async.commit_group;" ::: "memory")
#define CP_WAIT1()  asm volatile("cp.async.wait_group 1;" ::: "memory")
#define CP_WAIT0()  asm volatile("cp.async.wait_group 0;" ::: "memory")

__device__ __forceinline__ void mma_bf16(float c[4], const uint32_t a[4], const uint32_t b[2]) {
    asm volatile(
        "mma.sync.aligned.m16n8k16.row.col.f32.bf16.bf16.f32 "
        "{%0,%1,%2,%3}, {%4,%5,%6,%7}, {%8,%9}, {%0,%1,%2,%3};"
        : "+f"(c[0]), "+f"(c[1]), "+f"(c[2]), "+f"(c[3])
        : "r"(a[0]), "r"(a[1]), "r"(a[2]), "r"(a[3]), "r"(b[0]), "r"(b[1]));
}
// ldmatrix x4: canonical m16k16 A fragment (4x 8x8 b16 matrices)
__device__ __forceinline__ void ldsm_x4(uint32_t r[4], uint32_t addr) {
    asm volatile("ldmatrix.sync.aligned.m8n8.x4.shared.b16 {%0,%1,%2,%3}, [%4];"
        : "=r"(r[0]), "=r"(r[1]), "=r"(r[2]), "=r"(r[3]) : "r"(addr));
}
__device__ __forceinline__ float qmax(float v) {
    v = fmaxf(v, __shfl_xor_sync(0xffffffffu, v, 1));
    v = fmaxf(v, __shfl_xor_sync(0xffffffffu, v, 2));
    return v;
}
__device__ __forceinline__ float qsum(float v) {
    v += __shfl_xor_sync(0xffffffffu, v, 1);
    v += __shfl_xor_sync(0xffffffffu, v, 2);
    return v;
}

// ---------------- conversion kernels ----------------
// float4-vectorized: 4 output words (one k2-row quad) per thread
__global__ void __launch_bounds__(256) convw4_kernel(
    const float* __restrict__ W, uint32_t* __restrict__ hi, uint32_t* __restrict__ lo,
    int K, int N)
{
    size_t slice = (size_t)blockIdx.y;
    const float* Wp = W + slice * K * N;
    uint32_t* hp = hi + slice * (K/2) * N;
    uint32_t* lp = lo + slice * (K/2) * N;
    int q = blockIdx.x * 256 + threadIdx.x;   // quad index in [K/2 * N/4)
    int nquads = N >> 2;
    int nq = q % nquads, k2 = q / nquads;
    int n = nq * 4;
    float4 a = *(const float4*)(Wp + (size_t)(2*k2) * N + n);
    float4 b = *(const float4*)(Wp + (size_t)(2*k2+1) * N + n);
    uint4 hv, lv; float ra, rb;
    hv.x = pack_hi(a.x, b.x, ra, rb); lv.x = pack_lo(ra, rb);
    hv.y = pack_hi(a.y, b.y, ra, rb); lv.y = pack_lo(ra, rb);
    hv.z = pack_hi(a.z, b.z, ra, rb); lv.z = pack_lo(ra, rb);
    hv.w = pack_hi(a.w, b.w, ra, rb); lv.w = pack_lo(ra, rb);
    *(uint4*)(hp + (size_t)k2 * N + n) = hv;
    *(uint4*)(lp + (size_t)k2 * N + n) = lv;
}

__global__ void __launch_bounds__(256) conva_kernel(
    const float* __restrict__ A, uint32_t* __restrict__ hi, uint32_t* __restrict__ lo,
    int K2)
{
    int w = blockIdx.x * 256 + threadIdx.x;
    int k2 = w % K2, m = w / K2;
    float2 v = *(const float2*)(A + (size_t)m * (2*K2) + 2*k2);
    float ra, rb;
    hi[w] = pack_hi(v.x, v.y, ra, rb);
    lo[w] = pack_lo(ra, rb);
}

// rope + pack qkv into attention layouts; idx space = B*H*T*32 = 1M
__global__ void __launch_bounds__(256) ropeconv_kernel(
    const float* __restrict__ qkv,
    uint32_t* __restrict__ qh, uint32_t* __restrict__ ql,
    uint32_t* __restrict__ kh, uint32_t* __restrict__ kl,
    uint32_t* __restrict__ vh, uint32_t* __restrict__ vl)
{
    int idx = blockIdx.x * 256 + threadIdx.x;
    float ra, rb;
    const float LN1E4 = 9.210340371976184f;   // ln(10000)
    // Q: (b, h, t, p), p inner
    {
        int p = idx & 31, t = (idx >> 5) & 1023, hh = (idx >> 15) & 15, b = idx >> 19;
        size_t src = ((size_t)(b*T_ + t)*3 + 0)*D_ + hh*64 + 2*p;
        float x1 = qkv[src], x2 = qkv[src+1];
        float theta = (float)t * __expf(-(float)(2*((2*p) & 31)) * (1.f/64.f) * LN1E4);
        float sn, cs; sincosf(theta, &sn, &cs);
        float e = (x1*cs - x2*sn) * 0.125f;
        float o = (x1*sn + x2*cs) * 0.125f;
        size_t dst = ((size_t)(b*16 + hh)*T_ + t)*32 + p;
        qh[dst] = pack_hi(e, o, ra, rb); ql[dst] = pack_lo(ra, rb);
    }
    // K: (b, h, p, t), t inner -> transposed [d2][t]
    {
        int t = idx & 1023, p = (idx >> 10) & 31, hh = (idx >> 15) & 15, b = idx >> 19;
        size_t src = ((size_t)(b*T_ + t)*3 + 1)*D_ + hh*64 + 2*p;
        float x1 = qkv[src], x2 = qkv[src+1];
        float theta = (float)t * __expf(-(float)(2*((2*p) & 31)) * (1.f/64.f) * LN1E4);
        float sn, cs; sincosf(theta, &sn, &cs);
        float e = x1*cs - x2*sn;
        float o = x1*sn + x2*cs;
        size_t dst = ((size_t)(b*16 + hh)*32 + p)*T_ + t;
        kh[dst] = pack_hi(e, o, ra, rb); kl[dst] = pack_lo(ra, rb);
    }
    // V: (b, h, t2, d), d inner -> [t2][d] pairs across t
    {
        int d = idx & 63, t2 = (idx >> 6) & 511, hh = (idx >> 15) & 15, b = idx >> 19;
        size_t s0 = ((size_t)(b*T_ + 2*t2)*3 + 2)*D_ + hh*64 + d;
        float v0 = qkv[s0], v1 = qkv[s0 + 3*D_];
        size_t dst = ((size_t)(b*16 + hh)*512 + t2)*64 + d;
        vh[dst] = pack_hi(v0, v1, ra, rb); vl[dst] = pack_lo(ra, rb);
    }
}

// ================= bf16x3 mma.sync GEMM (templated on BN) =================
// C[M,N] = A[M,K] @ W[K,N] + bias (+ Res).  Operands pre-packed bf16x2 hi/lo.
// CTA 128 x BNv, 8 warps (2x4), warp tile 64x(BNv/4), BK=32, 3-stage cp.async.
// A fragments via ldmatrix.x4 (KP=20 stride is bank-conflict-free).
#define BM 128
#define BK 32
#define KP 20
#define A_STG (BM*KP)
#define NSTAGE 3
constexpr int smb(int BNv) { return NSTAGE * (2*A_STG + 2*16*(BNv + 8)) * 4; }

template<bool HAS_RES, int BNv>
__global__ void __launch_bounds__(256, 1) gemm_bf16x3(
    const uint32_t* __restrict__ Ah, const uint32_t* __restrict__ Al,
    const uint32_t* __restrict__ Wh, const uint32_t* __restrict__ Wl,
    const float* __restrict__ bias, const float* __restrict__ Res,
    float* __restrict__ C, int M, int N, int K)
{
    constexpr int NT    = BNv / 32;           // n-tiles per warp
    constexpr int BPADv = BNv + 8;
    constexpr int B_STGv = 16 * BPADv;
    constexpr int STG_Wv = 2*A_STG + 2*B_STGv;
    constexpr int TPR   = BNv / 4;            // threads per B k2-row
    constexpr int RPP   = 256 / TPR;          // rows per pass
    constexpr int NJ    = 16 / RPP;           // passes

    extern __shared__ uint32_t sm[];
    const uint32_t smem_base = smem_u32(sm);

    const int tid = threadIdx.x;
    const int lane = tid & 31, wid = tid >> 5;
    const int wm = wid >> 2, wn = wid & 3;
    const int m0 = blockIdx.y * BM, n0 = blockIdx.x * BNv;
    const int r = lane >> 2, cq = lane & 3;
    const int K2 = K >> 1;

    // ldmatrix per-lane address offsets (words): row/col of the 8x8 matrix this lane serves
    const int a_rowoff = ((lane >> 3) & 1) * 8 + (lane & 7);
    const int a_k2off  = (lane >> 4) * 4;

    float acc[4][NT][4];
    #pragma unroll
    for (int i = 0; i < 4; i++)
        #pragma unroll
        for (int j = 0; j < NT; j++)
            #pragma unroll
            for (int q = 0; q < 4; q++) acc[i][j][q] = 0.f;

    const int am = tid & 127, aqh = tid >> 7;
    const int nq = tid % TPR, k2b = tid / TPR;

    auto issue_loads = [&](int c, int s) {
        const int kc2 = c * 16;
        const uint32_t base = smem_base + (uint32_t)s * STG_Wv * 4;
        #pragma unroll
        for (int j = 0; j < 2; j++) {
            int q = aqh * 2 + j;
            cp16(base + (uint32_t)(am*KP + 4*q)*4, Ah + (size_t)(m0 + am) * K2 + kc2 + 4*q);
            cp16(base + (uint32_t)(A_STG + am*KP + 4*q)*4, Al + (size_t)(m0 + am) * K2 + kc2 + 4*q);
        }
        #pragma unroll
        for (int j = 0; j < NJ; j++) {
            int k2 = k2b + RPP*j;
            cp16(base + (uint32_t)(2*A_STG + k2*BPADv + 4*nq)*4, Wh + (size_t)(kc2 + k2) * N + n0 + 4*nq);
            cp16(base + (uint32_t)(2*A_STG + B_STGv + k2*BPADv + 4*nq)*4, Wl + (size_t)(kc2 + k2) * N + n0 + 4*nq);
        }
    };

    auto compute = [&](int s) {
        const uint32_t aHb = smem_base + (uint32_t)s * STG_Wv * 4;
        const uint32_t aLb = aHb + A_STG * 4;
        const uint32_t* BsH = sm + (size_t)s * STG_Wv + 2*A_STG;
        const uint32_t* BsL = BsH + B_STGv;
        #pragma unroll
        for (int ks = 0; ks < 2; ks++) {
            const int k2 = ks * 8 + cq;
            uint32_t ah[4][4], al[4][4], bh[NT][2], bl[NT][2];
            #pragma unroll
            for (int mt = 0; mt < 4; mt++) {
                uint32_t off = (uint32_t)((wm*64 + mt*16 + a_rowoff)*KP + ks*8 + a_k2off) * 4;
                ldsm_x4(ah[mt], aHb + off);
                ldsm_x4(al[mt], aLb + off);
            }
            #pragma unroll
            for (int nt = 0; nt < NT; nt++) {
                int n = wn*(BNv/4) + nt*8 + r;
                bh[nt][0] = BsH[k2*BPADv + n];
                bh[nt][1] = BsH[(k2+4)*BPADv + n];
                bl[nt][0] = BsL[k2*BPADv + n];
                bl[nt][1] = BsL[(k2+4)*BPADv + n];
            }
            #pragma unroll
            for (int mt = 0; mt < 4; mt++)
                #pragma unroll
                for (int nt = 0; nt < NT; nt++) {
                    mma_bf16(acc[mt][nt], ah[mt], bl[nt]);
                    mma_bf16(acc[mt][nt], al[mt], bh[nt]);
                    mma_bf16(acc[mt][nt], ah[mt], bh[nt]);
                }
        }
    };

    const int NC = K / BK;
    issue_loads(0, 0); CP_COMMIT();
    issue_loads(1, 1); CP_COMMIT();

    for (int c = 0; c < NC; c++) {
        CP_WAIT1();
        __syncthreads();
        if (c + 2 < NC) issue_loads(c + 2, (c + 2) % NSTAGE);
        CP_COMMIT();
        compute(c % NSTAGE);
    }

    const int cb = cq * 2;
    #pragma unroll
    for (int mt = 0; mt < 4; mt++) {
        #pragma unroll
        for (int nt = 0; nt < NT; nt++) {
            int m = m0 + wm*64 + mt*16 + r;
            int n = n0 + wn*(BNv/4) + nt*8 + cb;
            float2 bv = *(const float2*)(bias + n);
            float2 v0, v1;
            v0.x = acc[mt][nt][0] + bv.x; v0.y = acc[mt][nt][1] + bv.y;
            v1.x = acc[mt][nt][2] + bv.x; v1.y = acc[mt][nt][3] + bv.y;
            if (HAS_RES) {
                float2 r0 = *(const float2*)(Res + (size_t)m * N + n);
                float2 r1 = *(const float2*)(Res + (size_t)(m + 8) * N + n);
                v0.x += r0.x; v0.y += r0.y; v1.x += r1.x; v1.y += r1.y;
            }
            *(float2*)(C + (size_t)m * N + n) = v0;
            *(float2*)(C + (size_t)(m + 8) * N + n) = v1;
        }
    }
}

// ================= fused flash attention =================
// grid: (T/128, B*H). 256 threads, 8 warps; warp owns 16 q-rows.
// Q fragments via ldmatrix.x4 (QP=36 stride is bank-conflict-free).
#define TQ 128
#define TK 128
#define QP 36
#define KB 132
#define VB 68
#define QH_OFF 0
#define QL_OFF 4608
#define KH_OFF 9216
#define KL_OFF (KH_OFF + 2*4224)
#define VH_OFF (KL_OFF + 2*4224)
#define VL_OFF (VH_OFF + 2*4352)
#define RB_OFF (VL_OFF + 2*4352)
#define ATT_SMEM_BYTES ((RB_OFF + 260)*4)

__global__ void __launch_bounds__(256, 1) attn_kernel(
    const uint32_t* __restrict__ qh, const uint32_t* __restrict__ ql,
    const uint32_t* __restrict__ kh, const uint32_t* __restrict__ kl,
    const uint32_t* __restrict__ vh, const uint32_t* __restrict__ vl,
    const float* __restrict__ relb,
    uint32_t* __restrict__ oh, uint32_t* __restrict__ ol)
{
    extern __shared__ uint32_t sm[];
    const uint32_t sb = smem_u32(sm);
    const int tid = threadIdx.x, lane = tid & 31, wid = tid >> 5;
    const int r = lane >> 2, cq = lane & 3;
    const int qt0 = blockIdx.x * TQ;
    const int bh = blockIdx.y;
    const int b = bh >> 4, h = bh & 15;

    const int a_rowoff = ((lane >> 3) & 1) * 8 + (lane & 7);
    const int a_k2off  = (lane >> 4) * 4;

    float* rb_s = (float*)(sm + RB_OFF);
    for (int i = tid; i < 2*MREL + 1; i += 256) rb_s[i] = relb[i * H_ + h];

    const size_t qbase = ((size_t)bh * T_ + qt0) * 32;
    const size_t kbase = (size_t)bh * 32 * T_;
    const size_t vbase = (size_t)bh * 512 * 64;

    // load Q tile (persistent)
    {
        int t = tid >> 1, u = tid & 1;
        #pragma unroll
        for (int i = 0; i < 4; i++) {
            int un = u + 2*i;
            cp16(sb + (uint32_t)(QH_OFF + t*QP + un*4)*4, qh + qbase + (size_t)t*32 + un*4);
            cp16(sb + (uint32_t)(QL_OFF + t*QP + un*4)*4, ql + qbase + (size_t)t*32 + un*4);
        }
    }
    auto load_kv = [&](int kt, int s) {
        int kt0 = kt * TK;
        {
            int d2 = tid >> 3, j = tid & 7;
            #pragma unroll
            for (int i = 0; i < 4; i++) {
                int un = j + 8*i;
                cp16(sb + (uint32_t)(KH_OFF + s*4224 + d2*KB + un*4)*4, kh + kbase + (size_t)d2*T_ + kt0 + un*4);
                cp16(sb + (uint32_t)(KL_OFF + s*4224 + d2*KB + un*4)*4, kl + kbase + (size_t)d2*T_ + kt0 + un*4);
            }
        }
        {
            int t2 = tid >> 2, u = tid & 3;
            #pragma unroll
            for (int i = 0; i < 4; i++) {
                int un = u + 4*i;
                cp16(sb + (uint32_t)(VH_OFF + s*4352 + t2*VB + un*4)*4, vh + vbase + (size_t)(kt0/2 + t2)*64 + un*4);
                cp16(sb + (uint32_t)(VL_OFF + s*4352 + t2*VB + un*4)*4, vl + vbase + (size_t)(kt0/2 + t2)*64 + un*4);
            }
        }
    };

    load_kv(0, 0);
    CP_COMMIT();
    CP_WAIT0();
    __syncthreads();

    const int wq = wid * 16;
    const int qi0 = qt0 + wq + r, qi1 = qi0 + 8;
    float m0 = -1e30f, m1 = -1e30f, l0 = 0.f, l1 = 0.f;
    float oacc[8][4];
    #pragma unroll
    for (int i = 0; i < 8; i++)
        #pragma unroll
        for (int q = 0; q < 4; q++) oacc[i][q] = 0.f;

    const int NKT = T_ / TK;
    for (int kt = 0; kt < NKT; kt++) {
        const int s = kt & 1;
        if (kt + 1 < NKT) load_kv(kt + 1, (kt + 1) & 1);
        CP_COMMIT();

        const uint32_t qHb = sb + QH_OFF*4;
        const uint32_t qLb = sb + QL_OFF*4;
        const uint32_t* KsH = sm + KH_OFF + s*4224;
        const uint32_t* KsL = sm + KL_OFF + s*4224;
        const uint32_t* VsH = sm + VH_OFF + s*4352;
        const uint32_t* VsL = sm + VL_OFF + s*4352;

        // ---- scores ----
        float sacc[16][4];
        #pragma unroll
        for (int nt = 0; nt < 16; nt++)
            #pragma unroll
            for (int q = 0; q < 4; q++) sacc[nt][q] = 0.f;

        #pragma unroll
        for (int ks = 0; ks < 4; ks++) {
            const int k2 = ks * 8 + cq;
            uint32_t a_h[4], a_l[4];
            uint32_t off = (uint32_t)((wq + a_rowoff)*QP + ks*8 + a_k2off) * 4;
            ldsm_x4(a_h, qHb + off);
            ldsm_x4(a_l, qLb + off);
            #pragma unroll
            for (int nt = 0; nt < 16; nt++) {
                uint32_t b_h[2], b_l[2];
                b_h[0] = KsH[k2*KB + nt*8 + r];
                b_h[1] = KsH[(k2+4)*KB + nt*8 + r];
                b_l[0] = KsL[k2*KB + nt*8 + r];
                b_l[1] = KsL[(k2+4)*KB + nt*8 + r];
                mma_bf16(sacc[nt], a_h, b_l);
                mma_bf16(sacc[nt], a_l, b_h);
                mma_bf16(sacc[nt], a_h, b_h);
            }
        }

        // ---- bias + online softmax ----
        float tm0 = -1e30f, tm1 = -1e30f;
        #pragma unroll
        for (int nt = 0; nt < 16; nt++) {
            int kj = kt*TK + nt*8 + 2*cq;
            int i00 = min(max(kj   - qi0, -MREL), MREL) + MREL;
            int i01 = min(max(kj+1 - qi0, -MREL), MREL) + MREL;
            int i10 = min(max(kj   - qi1, -MREL), MREL) + MREL;
            int i11 = min(max(kj+1 - qi1, -MREL), MREL) + MREL;
            sacc[nt][0] += rb_s[i00];
            sacc[nt][1] += rb_s[i01];
            sacc[nt][2] += rb_s[i10];
            sacc[nt][3] += rb_s[i11];
            tm0 = fmaxf(tm0, fmaxf(sacc[nt][0], sacc[nt][1]));
            tm1 = fmaxf(tm1, fmaxf(sacc[nt][2], sacc[nt][3]));
        }
        tm0 = qmax(tm0); tm1 = qmax(tm1);
        float nm0 = fmaxf(m0, tm0), nm1 = fmaxf(m1, tm1);
        float sc0 = __expf(m0 - nm0), sc1 = __expf(m1 - nm1);
        l0 *= sc0; l1 *= sc1;
        #pragma unroll
        for (int i = 0; i < 8; i++) {
            oacc[i][0] *= sc0; oacc[i][1] *= sc0;
            oacc[i][2] *= sc1; oacc[i][3] *= sc1;
        }
        float rs0 = 0.f, rs1 = 0.f;
        #pragma unroll
        for (int nt = 0; nt < 16; nt++) {
            float p0 = __expf(sacc[nt][0] - nm0);
            float p1 = __expf(sacc[nt][1] - nm0);
            float p2 = __expf(sacc[nt][2] - nm1);
            float p3 = __expf(sacc[nt][3] - nm1);
            sacc[nt][0] = p0; sacc[nt][1] = p1; sacc[nt][2] = p2; sacc[nt][3] = p3;
            rs0 += p0 + p1; rs1 += p2 + p3;
        }
        l0 += qsum(rs0); l1 += qsum(rs1);
        m0 = nm0; m1 = nm1;

        // ---- P @ V ----
        #pragma unroll
        for (int kk = 0; kk < 8; kk++) {
            uint32_t p_h[4], p_l[4];
            float ra, rb;
            p_h[0] = pack_hi(sacc[2*kk][0],   sacc[2*kk][1],   ra, rb); p_l[0] = pack_lo(ra, rb);
            p_h[1] = pack_hi(sacc[2*kk][2],   sacc[2*kk][3],   ra, rb); p_l[1] = pack_lo(ra, rb);
            p_h[2] = pack_hi(sacc[2*kk+1][0], sacc[2*kk+1][1], ra, rb); p_l[2] = pack_lo(ra, rb);
            p_h[3] = pack_hi(sacc[2*kk+1][2], sacc[2*kk+1][3], ra, rb); p_l[3] = pack_lo(ra, rb);
            const int t2 = kk * 8 + cq;
            #pragma unroll
            for (int ntd = 0; ntd < 8; ntd++) {
                uint32_t b_h[2], b_l[2];
                b_h[0] = VsH[t2*VB + ntd*8 + r];
                b_h[1] = VsH[(t2+4)*VB + ntd*8 + r];
                b_l[0] = VsL[t2*VB + ntd*8 + r];
                b_l[1] = VsL[(t2+4)*VB + ntd*8 + r];
                mma_bf16(oacc[ntd], p_h, b_l);
                mma_bf16(oacc[ntd], p_l, b_h);
                mma_bf16(oacc[ntd], p_h, b_h);
            }
        }

        CP_WAIT0();
        __syncthreads();
    }

    // ---- finalize + packed store (feeds proj GEMM) ----
    float inv0 = 1.f / l0, inv1 = 1.f / l1;
    const size_t ob0 = ((size_t)(b*T_ + qt0 + wq + r))*512 + h*32;
    const size_t ob1 = ((size_t)(b*T_ + qt0 + wq + r + 8))*512 + h*32;
    #pragma unroll
    for (int ntd = 0; ntd < 8; ntd++) {
        int d2 = ntd*4 + cq;
        float ra, rb;
        uint32_t w0 = pack_hi(oacc[ntd][0]*inv0, oacc[ntd][1]*inv0, ra, rb);
        uint32_t w0l = pack_lo(ra, rb);
        uint32_t w1 = pack_hi(oacc[ntd][2]*inv1, oacc[ntd][3]*inv1, ra, rb);
        uint32_t w1l = pack_lo(ra, rb);
        oh[ob0 + d2] = w0; ol[ob0 + d2] = w0l;
        oh[ob1 + d2] = w1; ol[ob1 + d2] = w1l;
    }
}

// ---------------- block reduction ----------------
__device__ __forceinline__ float block_reduce_sum(float v) {
    __shared__ float sh[33];
    int lane = threadIdx.x & 31, wid = threadIdx.x >> 5;
    #pragma unroll
    for (int o = 16; o > 0; o >>= 1) v += __shfl_xor_sync(0xffffffffu, v, o);
    if (lane == 0) sh[wid] = v;
    __syncthreads();
    if (wid == 0) {
        float t = (lane < 8) ? sh[lane] : 0.f;
        #pragma unroll
        for (int o = 4; o > 0; o >>= 1) t += __shfl_xor_sync(0xffffffffu, t, o);
        if (lane == 0) sh[32] = t;
    }
    __syncthreads();
    return sh[32];
}

// ---------------- LayerNorm fp32 out (for ln_in only) ----------------
__global__ void __launch_bounds__(256) ln_kernel(
    const float* __restrict__ x, const float* __restrict__ g,
    const float* __restrict__ b, float* __restrict__ y)
{
    int row = blockIdx.x;
    const float* xr = x + (size_t)row * D_;
    float v[4];
    float s = 0.f;
    #pragma unroll
    for (int j = 0; j < 4; j++) { v[j] = xr[threadIdx.x + j * 256]; s += v[j]; }
    float mean = block_reduce_sum(s) * (1.0f / D_);
    float var = 0.f;
    #pragma unroll
    for (int j = 0; j < 4; j++) { float d0 = v[j] - mean; var += d0 * d0; }
    var = block_reduce_sum(var) * (1.0f / D_);
    float rstd = rsqrtf(var + 1e-5f);
    float* yr = y + (size_t)row * D_;
    #pragma unroll
    for (int j = 0; j < 4; j++) {
        int c = threadIdx.x + j * 256;
        yr[c] = (v[j] - mean) * rstd * g[c] + b[c];
    }
}

// ---------------- LayerNorm -> packed hi/lo (feeds GEMMs) ----------------
__global__ void __launch_bounds__(256) ln_pack_kernel(
    const float* __restrict__ x, const float* __restrict__ g,
    const float* __restrict__ b, uint32_t* __restrict__ ah, uint32_t* __restrict__ al)
{
    int row = blockIdx.x;
    const float* xr = x + (size_t)row * D_;
    float4 v = *(const float4*)(xr + threadIdx.x * 4);
    float s = v.x + v.y + v.z + v.w;
    float mean = block_reduce_sum(s) * (1.0f / D_);
    float dx = v.x - mean, dy = v.y - mean, dz = v.z - mean, dw = v.w - mean;
    float var = dx*dx + dy*dy + dz*dz + dw*dw;
    var = block_reduce_sum(var) * (1.0f / D_);
    float rstd = rsqrtf(var + 1e-5f);
    int c = threadIdx.x * 4;
    float4 gg = *(const float4*)(g + c);
    float4 bb = *(const float4*)(b + c);
    float y0 = dx * rstd * gg.x + bb.x;
    float y1 = dy * rstd * gg.y + bb.y;
    float y2 = dz * rstd * gg.z + bb.z;
    float y3 = dw * rstd * gg.w + bb.w;
    float ra, rb;
    size_t base = (size_t)row * 512 + threadIdx.x * 2;
    ah[base]   = pack_hi(y0, y1, ra, rb); al[base]   = pack_lo(ra, rb);
    ah[base+1] = pack_hi(y2, y3, ra, rb); al[base+1] = pack_lo(ra, rb);
}

// ---------------- GeGLU -> packed hi/lo ----------------
__global__ void __launch_bounds__(256) geglu_pack_kernel(
    const float* __restrict__ ff1, uint32_t* __restrict__ ah, uint32_t* __restrict__ al)
{
    int idx = blockIdx.x * 256 + threadIdx.x;   // BT * 2048
    int m = idx >> 11, f2 = idx & 2047;
    float2 a = *(const float2*)(ff1 + (size_t)m * (2*FF_) + 2*f2);
    float2 g = *(const float2*)(ff1 + (size_t)m * (2*FF_) + FF_ + 2*f2);
    float ge0 = 0.5f * g.x * (1.0f + erff(g.x * 0.70710678118654752f));
    float ge1 = 0.5f * g.y * (1.0f + erff(g.y * 0.70710678118654752f));
    float v0 = a.x * ge0, v1 = a.y * ge1;
    float ra, rb;
    ah[idx] = pack_hi(v0, v1, ra, rb);
    al[idx] = pack_lo(ra, rb);
}

// ---------------- final scaling epilogue ----------------
__global__ void __launch_bounds__(256) final_kernel(
    const float* __restrict__ o, const float* __restrict__ alpha,
    const float* __restrict__ beta, const float* __restrict__ alpha_scale,
    const float* __restrict__ beta_scale, float* __restrict__ out)
{
    int row = blockIdx.x;
    const float* orow = o + (size_t)row * D_;
    float v[4];
    float ss = 0.f;
    #pragma unroll
    for (int j = 0; j < 4; j++) { v[j] = orow[threadIdx.x + j * 256]; ss += v[j] * v[j]; }
    ss = block_reduce_sum(ss);
    float ms = sqrtf(ss);
    float a_s = fminf(fmaxf(alpha_scale[0], 0.f), 1.f);
    float sc = 1.0f + alpha[0] * a_s * fminf(ms, 5.0f);
    float bb = beta[0] * beta_scale[0];
    #pragma unroll
    for (int j = 0; j < 4; j++) {
        int c = threadIdx.x + j * 256;
        float val = v[j] * sc + bb;
        val = fminf(fmaxf(val, -10.0f), 10.0f);
        out[(size_t)row * D_ + c] = val + v[j];
    }
}

// ---------------- launch ----------------
extern "C" void kernel_launch(void* const* d_in, const int* in_sizes, int n_in,
                              void* d_out, int out_size)
{
    const float* x           = (const float*)d_in[0];
    const float* context     = (const float*)d_in[1];
    const float* W_in        = (const float*)d_in[2];
    const float* b_in        = (const float*)d_in[3];
    const float* ln_in_g     = (const float*)d_in[4];
    const float* ln_in_b     = (const float*)d_in[5];
    const float* ln1_g       = (const float*)d_in[6];
    const float* ln1_b       = (const float*)d_in[7];
    const float* Wqkv        = (const float*)d_in[8];
    const float* bqkv        = (const float*)d_in[9];
    const float* Wproj       = (const float*)d_in[10];
    const float* bproj       = (const float*)d_in[11];
    const float* rel_bias    = (const float*)d_in[12];
    const float* ln2_g       = (const float*)d_in[13];
    const float* ln2_b       = (const float*)d_in[14];
    const float* Wfc1        = (const float*)d_in[15];
    const float* bfc1        = (const float*)d_in[16];
    const float* Wfc2        = (const float*)d_in[17];
    const float* bfc2        = (const float*)d_in[18];
    const float* ln_f_g      = (const float*)d_in[19];
    const float* ln_f_b      = (const float*)d_in[20];
    const float* W_out       = (const float*)d_in[21];
    const float* b_out       = (const float*)d_in[22];
    const float* alpha       = (const float*)d_in[23];
    const float* beta        = (const float*)d_in[24];
    const float* alpha_scale = (const float*)d_in[25];
    const float* beta_scale  = (const float*)d_in[26];
    float* out = (float*)d_out;

    float *h, *tmp, *qkv, *ff1;
    uint32_t *ah, *al, *wh, *wl, *qh, *ql, *kh, *kl, *vh, *vl;
    cudaGetSymbolAddress((void**)&h,   g_h);
    cudaGetSymbolAddress((void**)&tmp, g_tmp);
    cudaGetSymbolAddress((void**)&qkv, g_qkv);
    cudaGetSymbolAddress((void**)&ff1, g_ff1);
    cudaGetSymbolAddress((void**)&ah,  g_ah);
    cudaGetSymbolAddress((void**)&al,  g_al);
    cudaGetSymbolAddress((void**)&wh,  g_wh);
    cudaGetSymbolAddress((void**)&wl,  g_wl);
    cudaGetSymbolAddress((void**)&qh,  g_qh);
    cudaGetSymbolAddress((void**)&ql,  g_ql);
    cudaGetSymbolAddress((void**)&kh,  g_kh);
    cudaGetSymbolAddress((void**)&kl,  g_kl);
    cudaGetSymbolAddress((void**)&vh,  g_vh);
    cudaGetSymbolAddress((void**)&vl,  g_vl);

    cudaFuncSetAttribute(gemm_bf16x3<true,256>,  cudaFuncAttributeMaxDynamicSharedMemorySize, smb(256));
    cudaFuncSetAttribute(gemm_bf16x3<false,256>, cudaFuncAttributeMaxDynamicSharedMemorySize, smb(256));
    cudaFuncSetAttribute(gemm_bf16x3<true,128>,  cudaFuncAttributeMaxDynamicSharedMemorySize, smb(128));
    cudaFuncSetAttribute(gemm_bf16x3<false,128>, cudaFuncAttributeMaxDynamicSharedMemorySize, smb(128));
    cudaFuncSetAttribute(attn_kernel, cudaFuncAttributeMaxDynamicSharedMemorySize, ATT_SMEM_BYTES);

    #define GEMM_W(RES, N, K, WOFF, bias, res, dst) \
        gemm_bf16x3<RES,256><<<dim3((N)/256, BT_/BM), 256, smb(256)>>>( \
            ah, al, wh + (WOFF), wl + (WOFF), (bias), (res), (dst), BT_, (N), (K))
    #define GEMM_N(RES, N, K, WOFF, bias, res, dst) \
        gemm_bf16x3<RES,128><<<dim3((N)/128, BT_/BM), 256, smb(128)>>>( \
            ah, al, wh + (WOFF), wl + (WOFF), (bias), (res), (dst), BT_, (N), (K))

    // ---- launch order arranged so ncu (-s 5 -c 1) captures launch #5 = gemm_bf16x3 ----
    convw4_kernel<<<dim3((int)(WSZ_IN/4/256), 1),   256>>>(W_in,  wh + WOFF_IN,   wl + WOFF_IN,   D_,  D_);   // 0
    conva_kernel<<<(BT_*D_/2)/256, 256>>>(x, ah, al, D_/2);                                                   // 1
    convw4_kernel<<<dim3((int)(WSZ_QKV/4/256), L_), 256>>>(Wqkv,  wh + WOFF_QKV,  wl + WOFF_QKV,  D_,  3*D_); // 2
    convw4_kernel<<<dim3((int)(WSZ_PROJ/4/256), L_),256>>>(Wproj, wh + WOFF_PROJ, wl + WOFF_PROJ, D_,  D_);   // 3
    convw4_kernel<<<dim3((int)(WSZ_FC1/4/256), L_), 256>>>(Wfc1,  wh + WOFF_FC1,  wl + WOFF_FC1,  D_,  2*FF_);// 4
    GEMM_N(true, D_, D_, WOFF_IN, b_in, context, tmp);                                                        // 5 <- ncu
    convw4_kernel<<<dim3((int)(WSZ_FC2/4/256), L_), 256>>>(Wfc2,  wh + WOFF_FC2,  wl + WOFF_FC2,  FF_, D_);
    convw4_kernel<<<dim3((int)(WSZ_IN/4/256), 1),   256>>>(W_out, wh + WOFF_OUT,  wl + WOFF_OUT,  D_,  D_);
    ln_kernel<<<BT_, 256>>>(tmp, ln_in_g, ln_in_b, h);

    for (int l = 0; l < L_; l++) {
        // attention block
        ln_pack_kernel<<<BT_, 256>>>(h, ln1_g + l*D_, ln1_b + l*D_, ah, al);
        GEMM_W(false, 3*D_, D_, WOFF_QKV + (size_t)l*WSZ_QKV, bqkv + l*3*D_, nullptr, qkv);
        ropeconv_kernel<<<(B_*H_*T_*32)/256, 256>>>(qkv, qh, ql, kh, kl, vh, vl);
        attn_kernel<<<dim3(T_/TQ, B_*H_), 256, ATT_SMEM_BYTES>>>(
            qh, ql, kh, kl, vh, vl, rel_bias + (size_t)l*(2*MREL+1)*H_, ah, al);
        GEMM_N(true, D_, D_, WOFF_PROJ + (size_t)l*WSZ_PROJ, bproj + l*D_, h, h);

        // FFN block
        ln_pack_kernel<<<BT_, 256>>>(h, ln2_g + l*D_, ln2_b + l*D_, ah, al);
        GEMM_W(false, 2*FF_, D_, WOFF_FC1 + (size_t)l*WSZ_FC1, bfc1 + l*2*FF_, nullptr, ff1);
        geglu_pack_kernel<<<(BT_*FF_/2)/256, 256>>>(ff1, ah, al);
        GEMM_N(true, D_, FF_, WOFF_FC2 + (size_t)l*WSZ_FC2, bfc2 + l*D_, h, h);
    }

    // post
    ln_pack_kernel<<<BT_, 256>>>(h, ln_f_g, ln_f_b, ah, al);
    GEMM_N(false, D_, D_, WOFF_OUT, b_out, nullptr, tmp);
    final_kernel<<<BT_, 256>>>(tmp, alpha, beta, alpha_scale, beta_scale, out);
}

// round 17
// speedup vs baseline: 1.0096x; 1.0096x over previous
#include <cuda_runtime.h>
#include <cuda_bf16.h>
#include <math.h>
#include <stdint.h>

#define B_  2
#define T_  1024
#define D_  1024
#define H_  16
#define HD_ 64
#define FF_ 4096
#define L_  4
#define MREL 128
#define BT_ (B_*T_)   // 2048

// ---------------- scratch (no allocs allowed) ----------------
__device__ float g_h[BT_*D_];          // 8 MB
__device__ float g_tmp[BT_*D_];        // 8 MB
__device__ float g_qkv[BT_*3*D_];      // 24 MB

// bf16x2-packed activations (hi/lo)
__device__ uint32_t g_ah[(size_t)BT_*D_/2];    // GEMM A inputs (K<=1024)
__device__ uint32_t g_al[(size_t)BT_*D_/2];
__device__ uint32_t g_bh[(size_t)BT_*FF_/2];   // geglu output (fc2 input, K=4096)
__device__ uint32_t g_bl[(size_t)BT_*FF_/2];

// attention operands, bf16x2 words
__device__ uint32_t g_qh[(size_t)B_*H_*T_*32];  // [bh][t][d2]
__device__ uint32_t g_ql[(size_t)B_*H_*T_*32];
__device__ uint32_t g_kh[(size_t)B_*H_*32*T_];  // [bh][d2][t]
__device__ uint32_t g_kl[(size_t)B_*H_*32*T_];
__device__ uint32_t g_vh[(size_t)B_*H_*512*64]; // [bh][t2][d]
__device__ uint32_t g_vl[(size_t)B_*H_*512*64];

// bf16x2-packed weights (hi/lo), word layout [K/2][N]  (fc1 columns interleaved a/g)
#define WOFF_IN   ((size_t)0)
#define WSZ_IN    ((size_t)D_*D_/2)
#define WOFF_QKV  (WOFF_IN + WSZ_IN)
#define WSZ_QKV   ((size_t)D_*3*D_/2)
#define WOFF_PROJ (WOFF_QKV + L_*WSZ_QKV)
#define WSZ_PROJ  ((size_t)D_*D_/2)
#define WOFF_FC1  (WOFF_PROJ + L_*WSZ_PROJ)
#define WSZ_FC1   ((size_t)D_*2*FF_/2)
#define WOFF_FC2  (WOFF_FC1 + L_*WSZ_FC1)
#define WSZ_FC2   ((size_t)FF_*D_/2)
#define WOFF_OUT  (WOFF_FC2 + L_*WSZ_FC2)
#define WTOT      (WOFF_OUT + (size_t)D_*D_/2)
__device__ uint32_t g_wh[WTOT];
__device__ uint32_t g_wl[WTOT];

// ---------------- helpers ----------------
__device__ __forceinline__ uint32_t smem_u32(const void* p) {
    uint32_t a;
    asm("{ .reg .u64 t; cvta.to.shared.u64 t, %1; cvt.u32.u64 %0, t; }" : "=r"(a) : "l"(p));
    return a;
}
__device__ __forceinline__ uint32_t pack_hi(float a, float b, float& ra, float& rb) {
    __nv_bfloat16 ba = __float2bfloat16_rn(a), bb = __float2bfloat16_rn(b);
    ra = a - __bfloat162float(ba);
    rb = b - __bfloat162float(bb);
    uint16_t ua = *(uint16_t*)&ba, ub = *(uint16_t*)&bb;
    return (uint32_t)ua | ((uint32_t)ub << 16);
}
__device__ __forceinline__ uint32_t pack_lo(float ra, float rb) {
    __nv_bfloat16 ba = __float2bfloat16_rn(ra), bb = __float2bfloat16_rn(rb);
    uint16_t ua = *(uint16_t*)&ba, ub = *(uint16_t*)&bb;
    return (uint32_t)ua | ((uint32_t)ub << 16);
}
__device__ __forceinline__ void cp16(uint32_t dst, const void* src) {
    asm volatile("cp.async.cg.shared.global [%0], [%1], 16;" :: "r"(dst), "l"(src));
}
#define CP_COMMIT() asm volatile("cp.async.commit_group;" ::: "memory")
#define CP_WAIT1()  asm volatile("cp.async.wait_group 1;" ::: "memory")
#define CP_WAIT0()  asm volatile("cp.async.wait_group 0;" ::: "memory")

__device__ __forceinline__ void mma_bf16(float c[4], const uint32_t a[4], const uint32_t b[2]) {
    asm volatile(
        "mma.sync.aligned.m16n8k16.row.col.f32.bf16.bf16.f32 "
        "{%0,%1,%2,%3}, {%4,%5,%6,%7}, {%8,%9}, {%0,%1,%2,%3};"
        : "+f"(c[0]), "+f"(c[1]), "+f"(c[2]), "+f"(c[3])
        : "r"(a[0]), "r"(a[1]), "r"(a[2]), "r"(a[3]), "r"(b[0]), "r"(b[1]));
}
__device__ __forceinline__ void ldsm_x4(uint32_t r[4], uint32_t addr) {
    asm volatile("ldmatrix.sync.aligned.m8n8.x4.shared.b16 {%0,%1,%2,%3}, [%4];"
        : "=r"(r[0]), "=r"(r[1]), "=r"(r[2]), "=r"(r[3]) : "r"(addr));
}
__device__ __forceinline__ float qmax(float v) {
    v = fmaxf(v, __shfl_xor_sync(0xffffffffu, v, 1));
    v = fmaxf(v, __shfl_xor_sync(0xffffffffu, v, 2));
    return v;
}
__device__ __forceinline__ float qsum(float v) {
    v += __shfl_xor_sync(0xffffffffu, v, 1);
    v += __shfl_xor_sync(0xffffffffu, v, 2);
    return v;
}

// ---------------- conversion kernels ----------------
__global__ void __launch_bounds__(256) convw4_kernel(
    const float* __restrict__ W, uint32_t* __restrict__ hi, uint32_t* __restrict__ lo,
    int K, int N)
{
    size_t slice = (size_t)blockIdx.y;
    const float* Wp = W + slice * K * N;
    uint32_t* hp = hi + slice * (K/2) * N;
    uint32_t* lp = lo + slice * (K/2) * N;
    int q = blockIdx.x * 256 + threadIdx.x;
    int nquads = N >> 2;
    int nq = q % nquads, k2 = q / nquads;
    int n = nq * 4;
    float4 a = *(const float4*)(Wp + (size_t)(2*k2) * N + n);
    float4 b = *(const float4*)(Wp + (size_t)(2*k2+1) * N + n);
    uint4 hv, lv; float ra, rb;
    hv.x = pack_hi(a.x, b.x, ra, rb); lv.x = pack_lo(ra, rb);
    hv.y = pack_hi(a.y, b.y, ra, rb); lv.y = pack_lo(ra, rb);
    hv.z = pack_hi(a.z, b.z, ra, rb); lv.z = pack_lo(ra, rb);
    hv.w = pack_hi(a.w, b.w, ra, rb); lv.w = pack_lo(ra, rb);
    *(uint4*)(hp + (size_t)k2 * N + n) = hv;
    *(uint4*)(lp + (size_t)k2 * N + n) = lv;
}

// fc1 weights with a/gate column interleave: permuted col n even -> a col n/2, odd -> gate col n/2
__global__ void __launch_bounds__(256) convw_fc1_kernel(
    const float* __restrict__ W, uint32_t* __restrict__ hi, uint32_t* __restrict__ lo)
{
    size_t slice = (size_t)blockIdx.y;
    const float* Wp = W + slice * (size_t)D_ * 2*FF_;
    uint32_t* hp = hi + slice * (size_t)(D_/2) * 2*FF_;
    uint32_t* lp = lo + slice * (size_t)(D_/2) * 2*FF_;
    int q = blockIdx.x * 256 + threadIdx.x;    // quad over (D/2 * 2FF/4)
    int nquads = (2*FF_) >> 2;
    int nq = q % nquads, k2 = q / nquads;
    int n = nq * 4;
    int f = n >> 1;
    const float* r0 = Wp + (size_t)(2*k2) * 2*FF_;
    const float* r1 = Wp + (size_t)(2*k2+1) * 2*FF_;
    float2 a0 = *(const float2*)(r0 + f);
    float2 g0 = *(const float2*)(r0 + FF_ + f);
    float2 a1 = *(const float2*)(r1 + f);
    float2 g1 = *(const float2*)(r1 + FF_ + f);
    uint4 hv, lv; float ra, rb;
    hv.x = pack_hi(a0.x, a1.x, ra, rb); lv.x = pack_lo(ra, rb);  // col n   = a(f)
    hv.y = pack_hi(g0.x, g1.x, ra, rb); lv.y = pack_lo(ra, rb);  // col n+1 = g(f)
    hv.z = pack_hi(a0.y, a1.y, ra, rb); lv.z = pack_lo(ra, rb);  // col n+2 = a(f+1)
    hv.w = pack_hi(g0.y, g1.y, ra, rb); lv.w = pack_lo(ra, rb);  // col n+3 = g(f+1)
    *(uint4*)(hp + (size_t)k2 * 2*FF_ + n) = hv;
    *(uint4*)(lp + (size_t)k2 * 2*FF_ + n) = lv;
}

__global__ void __launch_bounds__(256) conva_kernel(
    const float* __restrict__ A, uint32_t* __restrict__ hi, uint32_t* __restrict__ lo,
    int K2)
{
    int w = blockIdx.x * 256 + threadIdx.x;
    int k2 = w % K2, m = w / K2;
    float2 v = *(const float2*)(A + (size_t)m * (2*K2) + 2*k2);
    float ra, rb;
    hi[w] = pack_hi(v.x, v.y, ra, rb);
    lo[w] = pack_lo(ra, rb);
}

// rope + pack qkv into attention layouts; idx space = B*H*T*32 = 1M
__global__ void __launch_bounds__(256) ropeconv_kernel(
    const float* __restrict__ qkv,
    uint32_t* __restrict__ qh, uint32_t* __restrict__ ql,
    uint32_t* __restrict__ kh, uint32_t* __restrict__ kl,
    uint32_t* __restrict__ vh, uint32_t* __restrict__ vl)
{
    int idx = blockIdx.x * 256 + threadIdx.x;
    float ra, rb;
    const float LN1E4 = 9.210340371976184f;   // ln(10000)
    // Q: (b, h, t, p), p inner
    {
        int p = idx & 31, t = (idx >> 5) & 1023, hh = (idx >> 15) & 15, b = idx >> 19;
        size_t src = ((size_t)(b*T_ + t)*3 + 0)*D_ + hh*64 + 2*p;
        float x1 = qkv[src], x2 = qkv[src+1];
        float theta = (float)t * __expf(-(float)(2*((2*p) & 31)) * (1.f/64.f) * LN1E4);
        float sn, cs; sincosf(theta, &sn, &cs);
        float e = (x1*cs - x2*sn) * 0.125f;
        float o = (x1*sn + x2*cs) * 0.125f;
        size_t dst = ((size_t)(b*16 + hh)*T_ + t)*32 + p;
        qh[dst] = pack_hi(e, o, ra, rb); ql[dst] = pack_lo(ra, rb);
    }
    // K: (b, h, p, t), t inner -> transposed [d2][t]
    {
        int t = idx & 1023, p = (idx >> 10) & 31, hh = (idx >> 15) & 15, b = idx >> 19;
        size_t src = ((size_t)(b*T_ + t)*3 + 1)*D_ + hh*64 + 2*p;
        float x1 = qkv[src], x2 = qkv[src+1];
        float theta = (float)t * __expf(-(float)(2*((2*p) & 31)) * (1.f/64.f) * LN1E4);
        float sn, cs; sincosf(theta, &sn, &cs);
        float e = x1*cs - x2*sn;
        float o = x1*sn + x2*cs;
        size_t dst = ((size_t)(b*16 + hh)*32 + p)*T_ + t;
        kh[dst] = pack_hi(e, o, ra, rb); kl[dst] = pack_lo(ra, rb);
    }
    // V: (b, h, t2, d), d inner -> [t2][d] pairs across t
    {
        int d = idx & 63, t2 = (idx >> 6) & 511, hh = (idx >> 15) & 15, b = idx >> 19;
        size_t s0 = ((size_t)(b*T_ + 2*t2)*3 + 2)*D_ + hh*64 + d;
        float v0 = qkv[s0], v1 = qkv[s0 + 3*D_];
        size_t dst = ((size_t)(b*16 + hh)*512 + t2)*64 + d;
        vh[dst] = pack_hi(v0, v1, ra, rb); vl[dst] = pack_lo(ra, rb);
    }
}

// ================= bf16x3 mma.sync GEMM =================
// MODE 0: C = A@W + bias;  MODE 1: += Res;  MODE 2: geglu epilogue -> packed Oh/Ol.
#define BM 128
#define NSTAGE 3
constexpr int smb(int BNv, int BKv) {
    return NSTAGE * (2*BM*(BKv/2 + 4) + 2*(BKv/2)*(BNv + 8)) * 4;
}

template<int MODE, int BNv, int BKv>
__global__ void __launch_bounds__(256, 1) gemm_bf16x3(
    const uint32_t* __restrict__ Ah, const uint32_t* __restrict__ Al,
    const uint32_t* __restrict__ Wh, const uint32_t* __restrict__ Wl,
    const float* __restrict__ bias, const float* __restrict__ Res,
    float* __restrict__ C, uint32_t* __restrict__ Oh, uint32_t* __restrict__ Ol,
    int M, int N, int K)
{
    constexpr int NT    = BNv / 32;
    constexpr int KPv   = BKv/2 + 4;
    constexpr int A_STGv = BM*KPv;
    constexpr int BROWS = BKv/2;
    constexpr int BPADv = BNv + 8;
    constexpr int B_STGv = BROWS*BPADv;
    constexpr int STG_Wv = 2*A_STGv + 2*B_STGv;
    constexpr int KSI   = BKv/16;
    constexpr int NQA   = BKv/16;
    constexpr int TPR   = BNv/4;
    constexpr int RPP   = 256/TPR;
    constexpr int NJ    = BROWS/RPP;

    extern __shared__ uint32_t sm[];
    const uint32_t smem_base = smem_u32(sm);

    const int tid = threadIdx.x;
    const int lane = tid & 31, wid = tid >> 5;
    const int wm = wid >> 2, wn = wid & 3;
    const int m0 = blockIdx.y * BM, n0 = blockIdx.x * BNv;
    const int r = lane >> 2, cq = lane & 3;
    const int K2 = K >> 1;

    const int a_rowoff = ((lane >> 3) & 1) * 8 + (lane & 7);
    const int a_k2off  = (lane >> 4) * 4;

    float acc[4][NT][4];
    #pragma unroll
    for (int i = 0; i < 4; i++)
        #pragma unroll
        for (int j = 0; j < NT; j++)
            #pragma unroll
            for (int q = 0; q < 4; q++) acc[i][j][q] = 0.f;

    const int am = tid & 127, aqh = tid >> 7;
    const int nq = tid % TPR, k2b = tid / TPR;

    auto issue_loads = [&](int c, int s) {
        const int kc2 = c * BROWS;
        const uint32_t base = smem_base + (uint32_t)s * STG_Wv * 4;
        #pragma unroll
        for (int j = 0; j < NQA; j++) {
            int q = aqh * NQA + j;
            cp16(base + (uint32_t)(am*KPv + 4*q)*4, Ah + (size_t)(m0 + am) * K2 + kc2 + 4*q);
            cp16(base + (uint32_t)(A_STGv + am*KPv + 4*q)*4, Al + (size_t)(m0 + am) * K2 + kc2 + 4*q);
        }
        #pragma unroll
        for (int j = 0; j < NJ; j++) {
            int k2 = k2b + RPP*j;
            cp16(base + (uint32_t)(2*A_STGv + k2*BPADv + 4*nq)*4, Wh + (size_t)(kc2 + k2) * N + n0 + 4*nq);
            cp16(base + (uint32_t)(2*A_STGv + B_STGv + k2*BPADv + 4*nq)*4, Wl + (size_t)(kc2 + k2) * N + n0 + 4*nq);
        }
    };

    auto compute = [&](int s) {
        const uint32_t aHb = smem_base + (uint32_t)s * STG_Wv * 4;
        const uint32_t aLb = aHb + A_STGv * 4;
        const uint32_t* BsH = sm + (size_t)s * STG_Wv + 2*A_STGv;
        const uint32_t* BsL = BsH + B_STGv;
        #pragma unroll
        for (int ks = 0; ks < KSI; ks++) {
            const int k2 = ks * 8 + cq;
            uint32_t ah[4][4], al[4][4], bh[NT][2], bl[NT][2];
            #pragma unroll
            for (int mt = 0; mt < 4; mt++) {
                uint32_t off = (uint32_t)((wm*64 + mt*16 + a_rowoff)*KPv + ks*8 + a_k2off) * 4;
                ldsm_x4(ah[mt], aHb + off);
                ldsm_x4(al[mt], aLb + off);
            }
            #pragma unroll
            for (int nt = 0; nt < NT; nt++) {
                int n = wn*(BNv/4) + nt*8 + r;
                bh[nt][0] = BsH[k2*BPADv + n];
                bh[nt][1] = BsH[(k2+4)*BPADv + n];
                bl[nt][0] = BsL[k2*BPADv + n];
                bl[nt][1] = BsL[(k2+4)*BPADv + n];
            }
            #pragma unroll
            for (int mt = 0; mt < 4; mt++)
                #pragma unroll
                for (int nt = 0; nt < NT; nt++) {
                    mma_bf16(acc[mt][nt], ah[mt], bl[nt]);
                    mma_bf16(acc[mt][nt], al[mt], bh[nt]);
                    mma_bf16(acc[mt][nt], ah[mt], bh[nt]);
                }
        }
    };

    const int NC = K / BKv;
    issue_loads(0, 0); CP_COMMIT();
    issue_loads(1, 1); CP_COMMIT();

    for (int c = 0; c < NC; c++) {
        CP_WAIT1();
        __syncthreads();
        if (c + 2 < NC) issue_loads(c + 2, (c + 2) % NSTAGE);
        CP_COMMIT();
        compute(c % NSTAGE);
    }

    const int cb = cq * 2;
    if (MODE == 2) {
        // geglu epilogue: cols interleaved (a, gate); write packed bf16x2 hi/lo
        #pragma unroll
        for (int mt = 0; mt < 4; mt++) {
            #pragma unroll
            for (int nt = 0; nt < NT; nt++) {
                int m = m0 + wm*64 + mt*16 + r;
                int n = n0 + wn*(BNv/4) + nt*8 + cb;
                int f = n >> 1;
                float a0v = acc[mt][nt][0] + bias[f];
                float g0v = acc[mt][nt][1] + bias[FF_ + f];
                float a1v = acc[mt][nt][2] + bias[f];
                float g1v = acc[mt][nt][3] + bias[FF_ + f];
                float ge0 = 0.5f * g0v * (1.0f + erff(g0v * 0.70710678118654752f));
                float ge1 = 0.5f * g1v * (1.0f + erff(g1v * 0.70710678118654752f));
                float v0 = a0v * ge0;
                float v1 = a1v * ge1;
                float w0 = __shfl_xor_sync(0xffffffffu, v0, 1);
                float w1 = __shfl_xor_sync(0xffffffffu, v1, 1);
                if (!(cq & 1)) {
                    float ra, rb;
                    size_t o0 = (size_t)m * (FF_/2) + (f >> 1);
                    size_t o1 = (size_t)(m + 8) * (FF_/2) + (f >> 1);
                    Oh[o0] = pack_hi(v0, w0, ra, rb); Ol[o0] = pack_lo(ra, rb);
                    Oh[o1] = pack_hi(v1, w1, ra, rb); Ol[o1] = pack_lo(ra, rb);
                }
            }
        }
    } else {
        #pragma unroll
        for (int mt = 0; mt < 4; mt++) {
            #pragma unroll
            for (int nt = 0; nt < NT; nt++) {
                int m = m0 + wm*64 + mt*16 + r;
                int n = n0 + wn*(BNv/4) + nt*8 + cb;
                float2 bv = *(const float2*)(bias + n);
                float2 v0, v1;
                v0.x = acc[mt][nt][0] + bv.x; v0.y = acc[mt][nt][1] + bv.y;
                v1.x = acc[mt][nt][2] + bv.x; v1.y = acc[mt][nt][3] + bv.y;
                if (MODE == 1) {
                    float2 r0 = *(const float2*)(Res + (size_t)m * N + n);
                    float2 r1 = *(const float2*)(Res + (size_t)(m + 8) * N + n);
                    v0.x += r0.x; v0.y += r0.y; v1.x += r1.x; v1.y += r1.y;
                }
                *(float2*)(C + (size_t)m * N + n) = v0;
                *(float2*)(C + (size_t)(m + 8) * N + n) = v1;
            }
        }
    }
}

// ================= fused flash attention =================
#define TQ 128
#define TK 128
#define QP 36
#define KB 132
#define VB 68
#define QH_OFF 0
#define QL_OFF 4608
#define KH_OFF 9216
#define KL_OFF (KH_OFF + 2*4224)
#define VH_OFF (KL_OFF + 2*4224)
#define VL_OFF (VH_OFF + 2*4352)
#define RB_OFF (VL_OFF + 2*4352)
#define ATT_SMEM_BYTES ((RB_OFF + 260)*4)

__global__ void __launch_bounds__(256, 1) attn_kernel(
    const uint32_t* __restrict__ qh, const uint32_t* __restrict__ ql,
    const uint32_t* __restrict__ kh, const uint32_t* __restrict__ kl,
    const uint32_t* __restrict__ vh, const uint32_t* __restrict__ vl,
    const float* __restrict__ relb,
    uint32_t* __restrict__ oh, uint32_t* __restrict__ ol)
{
    extern __shared__ uint32_t sm[];
    const uint32_t sb = smem_u32(sm);
    const int tid = threadIdx.x, lane = tid & 31, wid = tid >> 5;
    const int r = lane >> 2, cq = lane & 3;
    const int qt0 = blockIdx.x * TQ;
    const int bh = blockIdx.y;
    const int b = bh >> 4, h = bh & 15;

    const int a_rowoff = ((lane >> 3) & 1) * 8 + (lane & 7);
    const int a_k2off  = (lane >> 4) * 4;

    float* rb_s = (float*)(sm + RB_OFF);
    for (int i = tid; i < 2*MREL + 1; i += 256) rb_s[i] = relb[i * H_ + h];

    const size_t qbase = ((size_t)bh * T_ + qt0) * 32;
    const size_t kbase = (size_t)bh * 32 * T_;
    const size_t vbase = (size_t)bh * 512 * 64;

    {
        int t = tid >> 1, u = tid & 1;
        #pragma unroll
        for (int i = 0; i < 4; i++) {
            int un = u + 2*i;
            cp16(sb + (uint32_t)(QH_OFF + t*QP + un*4)*4, qh + qbase + (size_t)t*32 + un*4);
            cp16(sb + (uint32_t)(QL_OFF + t*QP + un*4)*4, ql + qbase + (size_t)t*32 + un*4);
        }
    }
    auto load_kv = [&](int kt, int s) {
        int kt0 = kt * TK;
        {
            int d2 = tid >> 3, j = tid & 7;
            #pragma unroll
            for (int i = 0; i < 4; i++) {
                int un = j + 8*i;
                cp16(sb + (uint32_t)(KH_OFF + s*4224 + d2*KB + un*4)*4, kh + kbase + (size_t)d2*T_ + kt0 + un*4);
                cp16(sb + (uint32_t)(KL_OFF + s*4224 + d2*KB + un*4)*4, kl + kbase + (size_t)d2*T_ + kt0 + un*4);
            }
        }
        {
            int t2 = tid >> 2, u = tid & 3;
            #pragma unroll
            for (int i = 0; i < 4; i++) {
                int un = u + 4*i;
                cp16(sb + (uint32_t)(VH_OFF + s*4352 + t2*VB + un*4)*4, vh + vbase + (size_t)(kt0/2 + t2)*64 + un*4);
                cp16(sb + (uint32_t)(VL_OFF + s*4352 + t2*VB + un*4)*4, vl + vbase + (size_t)(kt0/2 + t2)*64 + un*4);
            }
        }
    };

    load_kv(0, 0);
    CP_COMMIT();
    CP_WAIT0();
    __syncthreads();

    const int wq = wid * 16;
    const int qi0 = qt0 + wq + r, qi1 = qi0 + 8;
    float m0 = -1e30f, m1 = -1e30f, l0 = 0.f, l1 = 0.f;
    float oacc[8][4];
    #pragma unroll
    for (int i = 0; i < 8; i++)
        #pragma unroll
        for (int q = 0; q < 4; q++) oacc[i][q] = 0.f;

    const int NKT = T_ / TK;
    for (int kt = 0; kt < NKT; kt++) {
        const int s = kt & 1;
        if (kt + 1 < NKT) load_kv(kt + 1, (kt + 1) & 1);
        CP_COMMIT();

        const uint32_t qHb = sb + QH_OFF*4;
        const uint32_t qLb = sb + QL_OFF*4;
        const uint32_t* KsH = sm + KH_OFF + s*4224;
        const uint32_t* KsL = sm + KL_OFF + s*4224;
        const uint32_t* VsH = sm + VH_OFF + s*4352;
        const uint32_t* VsL = sm + VL_OFF + s*4352;

        float sacc[16][4];
        #pragma unroll
        for (int nt = 0; nt < 16; nt++)
            #pragma unroll
            for (int q = 0; q < 4; q++) sacc[nt][q] = 0.f;

        #pragma unroll
        for (int ks = 0; ks < 4; ks++) {
            const int k2 = ks * 8 + cq;
            uint32_t a_h[4], a_l[4];
            uint32_t off = (uint32_t)((wq + a_rowoff)*QP + ks*8 + a_k2off) * 4;
            ldsm_x4(a_h, qHb + off);
            ldsm_x4(a_l, qLb + off);
            #pragma unroll
            for (int nt = 0; nt < 16; nt++) {
                uint32_t b_h[2], b_l[2];
                b_h[0] = KsH[k2*KB + nt*8 + r];
                b_h[1] = KsH[(k2+4)*KB + nt*8 + r];
                b_l[0] = KsL[k2*KB + nt*8 + r];
                b_l[1] = KsL[(k2+4)*KB + nt*8 + r];
                mma_bf16(sacc[nt], a_h, b_l);
                mma_bf16(sacc[nt], a_l, b_h);
                mma_bf16(sacc[nt], a_h, b_h);
            }
        }

        float tm0 = -1e30f, tm1 = -1e30f;
        #pragma unroll
        for (int nt = 0; nt < 16; nt++) {
            int kj = kt*TK + nt*8 + 2*cq;
            int i00 = min(max(kj   - qi0, -MREL), MREL) + MREL;
            int i01 = min(max(kj+1 - qi0, -MREL), MREL) + MREL;
            int i10 = min(max(kj   - qi1, -MREL), MREL) + MREL;
            int i11 = min(max(kj+1 - qi1, -MREL), MREL) + MREL;
            sacc[nt][0] += rb_s[i00];
            sacc[nt][1] += rb_s[i01];
            sacc[nt][2] += rb_s[i10];
            sacc[nt][3] += rb_s[i11];
            tm0 = fmaxf(tm0, fmaxf(sacc[nt][0], sacc[nt][1]));
            tm1 = fmaxf(tm1, fmaxf(sacc[nt][2], sacc[nt][3]));
        }
        tm0 = qmax(tm0); tm1 = qmax(tm1);
        float nm0 = fmaxf(m0, tm0), nm1 = fmaxf(m1, tm1);
        float sc0 = __expf(m0 - nm0), sc1 = __expf(m1 - nm1);
        l0 *= sc0; l1 *= sc1;
        #pragma unroll
        for (int i = 0; i < 8; i++) {
            oacc[i][0] *= sc0; oacc[i][1] *= sc0;
            oacc[i][2] *= sc1; oacc[i][3] *= sc1;
        }
        float rs0 = 0.f, rs1 = 0.f;
        #pragma unroll
        for (int nt = 0; nt < 16; nt++) {
            float p0 = __expf(sacc[nt][0] - nm0);
            float p1 = __expf(sacc[nt][1] - nm0);
            float p2 = __expf(sacc[nt][2] - nm1);
            float p3 = __expf(sacc[nt][3] - nm1);
            sacc[nt][0] = p0; sacc[nt][1] = p1; sacc[nt][2] = p2; sacc[nt][3] = p3;
            rs0 += p0 + p1; rs1 += p2 + p3;
        }
        l0 += qsum(rs0); l1 += qsum(rs1);
        m0 = nm0; m1 = nm1;

        #pragma unroll
        for (int kk = 0; kk < 8; kk++) {
            uint32_t p_h[4], p_l[4];
            float ra, rb;
            p_h[0] = pack_hi(sacc[2*kk][0],   sacc[2*kk][1],   ra, rb); p_l[0] = pack_lo(ra, rb);
            p_h[1] = pack_hi(sacc[2*kk][2],   sacc[2*kk][3],   ra, rb); p_l[1] = pack_lo(ra, rb);
            p_h[2] = pack_hi(sacc[2*kk+1][0], sacc[2*kk+1][1], ra, rb); p_l[2] = pack_lo(ra, rb);
            p_h[3] = pack_hi(sacc[2*kk+1][2], sacc[2*kk+1][3], ra, rb); p_l[3] = pack_lo(ra, rb);
            const int t2 = kk * 8 + cq;
            #pragma unroll
            for (int ntd = 0; ntd < 8; ntd++) {
                uint32_t b_h[2], b_l[2];
                b_h[0] = VsH[t2*VB + ntd*8 + r];
                b_h[1] = VsH[(t2+4)*VB + ntd*8 + r];
                b_l[0] = VsL[t2*VB + ntd*8 + r];
                b_l[1] = VsL[(t2+4)*VB + ntd*8 + r];
                mma_bf16(oacc[ntd], p_h, b_l);
                mma_bf16(oacc[ntd], p_l, b_h);
                mma_bf16(oacc[ntd], p_h, b_h);
            }
        }

        CP_WAIT0();
        __syncthreads();
    }

    float inv0 = 1.f / l0, inv1 = 1.f / l1;
    const size_t ob0 = ((size_t)(b*T_ + qt0 + wq + r))*512 + h*32;
    const size_t ob1 = ((size_t)(b*T_ + qt0 + wq + r + 8))*512 + h*32;
    #pragma unroll
    for (int ntd = 0; ntd < 8; ntd++) {
        int d2 = ntd*4 + cq;
        float ra, rb;
        uint32_t w0 = pack_hi(oacc[ntd][0]*inv0, oacc[ntd][1]*inv0, ra, rb);
        uint32_t w0l = pack_lo(ra, rb);
        uint32_t w1 = pack_hi(oacc[ntd][2]*inv1, oacc[ntd][3]*inv1, ra, rb);
        uint32_t w1l = pack_lo(ra, rb);
        oh[ob0 + d2] = w0; ol[ob0 + d2] = w0l;
        oh[ob1 + d2] = w1; ol[ob1 + d2] = w1l;
    }
}

// ---------------- block reduction ----------------
__device__ __forceinline__ float block_reduce_sum(float v) {
    __shared__ float sh[33];
    int lane = threadIdx.x & 31, wid = threadIdx.x >> 5;
    #pragma unroll
    for (int o = 16; o > 0; o >>= 1) v += __shfl_xor_sync(0xffffffffu, v, o);
    if (lane == 0) sh[wid] = v;
    __syncthreads();
    if (wid == 0) {
        float t = (lane < 8) ? sh[lane] : 0.f;
        #pragma unroll
        for (int o = 4; o > 0; o >>= 1) t += __shfl_xor_sync(0xffffffffu, t, o);
        if (lane == 0) sh[32] = t;
    }
    __syncthreads();
    return sh[32];
}

// ---------------- LayerNorm fp32 out (for ln_in only) ----------------
__global__ void __launch_bounds__(256) ln_kernel(
    const float* __restrict__ x, const float* __restrict__ g,
    const float* __restrict__ b, float* __restrict__ y)
{
    int row = blockIdx.x;
    const float* xr = x + (size_t)row * D_;
    float v[4];
    float s = 0.f;
    #pragma unroll
    for (int j = 0; j < 4; j++) { v[j] = xr[threadIdx.x + j * 256]; s += v[j]; }
    float mean = block_reduce_sum(s) * (1.0f / D_);
    float var = 0.f;
    #pragma unroll
    for (int j = 0; j < 4; j++) { float d0 = v[j] - mean; var += d0 * d0; }
    var = block_reduce_sum(var) * (1.0f / D_);
    float rstd = rsqrtf(var + 1e-5f);
    float* yr = y + (size_t)row * D_;
    #pragma unroll
    for (int j = 0; j < 4; j++) {
        int c = threadIdx.x + j * 256;
        yr[c] = (v[j] - mean) * rstd * g[c] + b[c];
    }
}

// ---------------- LayerNorm -> packed hi/lo ----------------
__global__ void __launch_bounds__(256) ln_pack_kernel(
    const float* __restrict__ x, const float* __restrict__ g,
    const float* __restrict__ b, uint32_t* __restrict__ ah, uint32_t* __restrict__ al)
{
    int row = blockIdx.x;
    const float* xr = x + (size_t)row * D_;
    float4 v = *(const float4*)(xr + threadIdx.x * 4);
    float s = v.x + v.y + v.z + v.w;
    float mean = block_reduce_sum(s) * (1.0f / D_);
    float dx = v.x - mean, dy = v.y - mean, dz = v.z - mean, dw = v.w - mean;
    float var = dx*dx + dy*dy + dz*dz + dw*dw;
    var = block_reduce_sum(var) * (1.0f / D_);
    float rstd = rsqrtf(var + 1e-5f);
    int c = threadIdx.x * 4;
    float4 gg = *(const float4*)(g + c);
    float4 bb = *(const float4*)(b + c);
    float y0 = dx * rstd * gg.x + bb.x;
    float y1 = dy * rstd * gg.y + bb.y;
    float y2 = dz * rstd * gg.z + bb.z;
    float y3 = dw * rstd * gg.w + bb.w;
    float ra, rb;
    size_t base = (size_t)row * 512 + threadIdx.x * 2;
    ah[base]   = pack_hi(y0, y1, ra, rb); al[base]   = pack_lo(ra, rb);
    ah[base+1] = pack_hi(y2, y3, ra, rb); al[base+1] = pack_lo(ra, rb);
}

// ---------------- final scaling epilogue ----------------
__global__ void __launch_bounds__(256) final_kernel(
    const float* __restrict__ o, const float* __restrict__ alpha,
    const float* __restrict__ beta, const float* __restrict__ alpha_scale,
    const float* __restrict__ beta_scale, float* __restrict__ out)
{
    int row = blockIdx.x;
    const float* orow = o + (size_t)row * D_;
    float v[4];
    float ss = 0.f;
    #pragma unroll
    for (int j = 0; j < 4; j++) { v[j] = orow[threadIdx.x + j * 256]; ss += v[j] * v[j]; }
    ss = block_reduce_sum(ss);
    float ms = sqrtf(ss);
    float a_s = fminf(fmaxf(alpha_scale[0], 0.f), 1.f);
    float sc = 1.0f + alpha[0] * a_s * fminf(ms, 5.0f);
    float bb = beta[0] * beta_scale[0];
    #pragma unroll
    for (int j = 0; j < 4; j++) {
        int c = threadIdx.x + j * 256;
        float val = v[j] * sc + bb;
        val = fminf(fmaxf(val, -10.0f), 10.0f);
        out[(size_t)row * D_ + c] = val + v[j];
    }
}

// ---------------- launch ----------------
extern "C" void kernel_launch(void* const* d_in, const int* in_sizes, int n_in,
                              void* d_out, int out_size)
{
    const float* x           = (const float*)d_in[0];
    const float* context     = (const float*)d_in[1];
    const float* W_in        = (const float*)d_in[2];
    const float* b_in        = (const float*)d_in[3];
    const float* ln_in_g     = (const float*)d_in[4];
    const float* ln_in_b     = (const float*)d_in[5];
    const float* ln1_g       = (const float*)d_in[6];
    const float* ln1_b       = (const float*)d_in[7];
    const float* Wqkv        = (const float*)d_in[8];
    const float* bqkv        = (const float*)d_in[9];
    const float* Wproj       = (const float*)d_in[10];
    const float* bproj       = (const float*)d_in[11];
    const float* rel_bias    = (const float*)d_in[12];
    const float* ln2_g       = (const float*)d_in[13];
    const float* ln2_b       = (const float*)d_in[14];
    const float* Wfc1        = (const float*)d_in[15];
    const float* bfc1        = (const float*)d_in[16];
    const float* Wfc2        = (const float*)d_in[17];
    const float* bfc2        = (const float*)d_in[18];
    const float* ln_f_g      = (const float*)d_in[19];
    const float* ln_f_b      = (const float*)d_in[20];
    const float* W_out       = (const float*)d_in[21];
    const float* b_out       = (const float*)d_in[22];
    const float* alpha       = (const float*)d_in[23];
    const float* beta        = (const float*)d_in[24];
    const float* alpha_scale = (const float*)d_in[25];
    const float* beta_scale  = (const float*)d_in[26];
    float* out = (float*)d_out;

    float *h, *tmp, *qkv;
    uint32_t *ah, *al, *bh, *bl, *wh, *wl, *qh, *ql, *kh, *kl, *vh, *vl;
    cudaGetSymbolAddress((void**)&h,   g_h);
    cudaGetSymbolAddress((void**)&tmp, g_tmp);
    cudaGetSymbolAddress((void**)&qkv, g_qkv);
    cudaGetSymbolAddress((void**)&ah,  g_ah);
    cudaGetSymbolAddress((void**)&al,  g_al);
    cudaGetSymbolAddress((void**)&bh,  g_bh);
    cudaGetSymbolAddress((void**)&bl,  g_bl);
    cudaGetSymbolAddress((void**)&wh,  g_wh);
    cudaGetSymbolAddress((void**)&wl,  g_wl);
    cudaGetSymbolAddress((void**)&qh,  g_qh);
    cudaGetSymbolAddress((void**)&ql,  g_ql);
    cudaGetSymbolAddress((void**)&kh,  g_kh);
    cudaGetSymbolAddress((void**)&kl,  g_kl);
    cudaGetSymbolAddress((void**)&vh,  g_vh);
    cudaGetSymbolAddress((void**)&vl,  g_vl);

    cudaFuncSetAttribute(gemm_bf16x3<0,256,32>, cudaFuncAttributeMaxDynamicSharedMemorySize, smb(256,32));
    cudaFuncSetAttribute(gemm_bf16x3<2,256,32>, cudaFuncAttributeMaxDynamicSharedMemorySize, smb(256,32));
    cudaFuncSetAttribute(gemm_bf16x3<0,128,64>, cudaFuncAttributeMaxDynamicSharedMemorySize, smb(128,64));
    cudaFuncSetAttribute(gemm_bf16x3<1,128,64>, cudaFuncAttributeMaxDynamicSharedMemorySize, smb(128,64));
    cudaFuncSetAttribute(attn_kernel, cudaFuncAttributeMaxDynamicSharedMemorySize, ATT_SMEM_BYTES);

    // wide (BN=256, BK=32): qkv + fc1(geglu).  narrow (BN=128, BK=64): N=1024 GEMMs.
    #define GEMM_QKV(N, K, WOFF, bias, dst) \
        gemm_bf16x3<0,256,32><<<dim3((N)/256, BT_/BM), 256, smb(256,32)>>>( \
            ah, al, wh + (WOFF), wl + (WOFF), (bias), nullptr, (dst), nullptr, nullptr, BT_, (N), (K))
    #define GEMM_FC1(WOFF, bias) \
        gemm_bf16x3<2,256,32><<<dim3((2*FF_)/256, BT_/BM), 256, smb(256,32)>>>( \
            ah, al, wh + (WOFF), wl + (WOFF), (bias), nullptr, nullptr, bh, bl, BT_, 2*FF_, D_)
    #define GEMM_N0(N, K, Ain, Ail, WOFF, bias, dst) \
        gemm_bf16x3<0,128,64><<<dim3((N)/128, BT_/BM), 256, smb(128,64)>>>( \
            (Ain), (Ail), wh + (WOFF), wl + (WOFF), (bias), nullptr, (dst), nullptr, nullptr, BT_, (N), (K))
    #define GEMM_N1(N, K, Ain, Ail, WOFF, bias, res, dst) \
        gemm_bf16x3<1,128,64><<<dim3((N)/128, BT_/BM), 256, smb(128,64)>>>( \
            (Ain), (Ail), wh + (WOFF), wl + (WOFF), (bias), (res), (dst), nullptr, nullptr, BT_, (N), (K))

    // ---- weight pre-conversion ----
    convw4_kernel<<<dim3((int)(WSZ_IN/4/256), 1),   256>>>(W_in,  wh + WOFF_IN,   wl + WOFF_IN,   D_,  D_);
    conva_kernel<<<(BT_*D_/2)/256, 256>>>(x, ah, al, D_/2);
    convw4_kernel<<<dim3((int)(WSZ_QKV/4/256), L_), 256>>>(Wqkv,  wh + WOFF_QKV,  wl + WOFF_QKV,  D_,  3*D_);
    convw4_kernel<<<dim3((int)(WSZ_PROJ/4/256), L_),256>>>(Wproj, wh + WOFF_PROJ, wl + WOFF_PROJ, D_,  D_);
    convw_fc1_kernel<<<dim3((int)(WSZ_FC1/4/256), L_), 256>>>(Wfc1, wh + WOFF_FC1, wl + WOFF_FC1);
    GEMM_N1(D_, D_, ah, al, WOFF_IN, b_in, context, tmp);
    convw4_kernel<<<dim3((int)(WSZ_FC2/4/256), L_), 256>>>(Wfc2,  wh + WOFF_FC2,  wl + WOFF_FC2,  FF_, D_);
    convw4_kernel<<<dim3((int)(WSZ_IN/4/256), 1),   256>>>(W_out, wh + WOFF_OUT,  wl + WOFF_OUT,  D_,  D_);
    ln_kernel<<<BT_, 256>>>(tmp, ln_in_g, ln_in_b, h);

    for (int l = 0; l < L_; l++) {
        // attention block
        ln_pack_kernel<<<BT_, 256>>>(h, ln1_g + l*D_, ln1_b + l*D_, ah, al);
        GEMM_QKV(3*D_, D_, WOFF_QKV + (size_t)l*WSZ_QKV, bqkv + l*3*D_, qkv);
        ropeconv_kernel<<<(B_*H_*T_*32)/256, 256>>>(qkv, qh, ql, kh, kl, vh, vl);
        attn_kernel<<<dim3(T_/TQ, B_*H_), 256, ATT_SMEM_BYTES>>>(
            qh, ql, kh, kl, vh, vl, rel_bias + (size_t)l*(2*MREL+1)*H_, ah, al);
        GEMM_N1(D_, D_, ah, al, WOFF_PROJ + (size_t)l*WSZ_PROJ, bproj + l*D_, h, h);

        // FFN block (GeGLU fused into fc1 epilogue; output packed in bh/bl)
        ln_pack_kernel<<<BT_, 256>>>(h, ln2_g + l*D_, ln2_b + l*D_, ah, al);
        GEMM_FC1(WOFF_FC1 + (size_t)l*WSZ_FC1, bfc1 + l*2*FF_);
        GEMM_N1(D_, FF_, bh, bl, WOFF_FC2 + (size_t)l*WSZ_FC2, bfc2 + l*D_, h, h);
    }

    // post
    ln_pack_kernel<<<BT_, 256>>>(h, ln_f_g, ln_f_b, ah, al);
    GEMM_N0(D_, D_, ah, al, WOFF_OUT, b_out, tmp);
    final_kernel<<<BT_, 256>>>(tmp, alpha, beta, alpha_scale, beta_scale, out);
}